// round 4
// baseline (speedup 1.0000x reference)
#include <cuda_runtime.h>

#define THREADS 512
#define IMH 256
#define IMW 256

typedef unsigned long long ull;

__device__ __forceinline__ ull pk(float a, float b) {
    ull r; asm("mov.b64 %0,{%1,%2};" : "=l"(r) : "f"(a), "f"(b)); return r;
}
__device__ __forceinline__ float2 upk(ull v) {
    float2 f; asm("mov.b64 {%0,%1},%2;" : "=f"(f.x), "=f"(f.y) : "l"(v)); return f;
}
__device__ __forceinline__ ull fma2(ull a, ull b, ull c) {
    ull d; asm("fma.rn.f32x2 %0,%1,%2,%3;" : "=l"(d) : "l"(a), "l"(b), "l"(c)); return d;
}

// shared memory offsets (floats) — identical to round-3 layout
#define OFF_XS    0          // [64][128] x tile; overlaid by wpT[128][68] after Phase A
#define OFF_WPT   0
#define OFF_WS    8192       // [64][132] staged w_hidden pass chunk, transposed
#define OFF_HS    16640      // [64][128] hidden scratch (one 64-ch half)
#define OFF_WDWP  24832      // [128][9] dw weights for pass
#define OFF_Q     25984      // [128][68]
#define OFF_K     34688      // [128][68]
#define OFF_V     43392      // [128][68]
#define OFF_PS    52096      // [8][66]
#define OFF_PQ    52624      // [8][66]
#define OFF_MEAN  53152      // [64]
#define OFF_RSTD  53216      // [64]
#define SMEM_FLOATS 53280    // 213120 bytes

extern __shared__ float smem[];

__global__ __launch_bounds__(THREADS, 1)
void fsas_kernel(const float* __restrict__ x,
                 const float* __restrict__ w_hidden,
                 const float* __restrict__ b_hidden,
                 const float* __restrict__ w_dw,
                 const float* __restrict__ b_dw,
                 const float* __restrict__ w_proj,
                 const float* __restrict__ b_proj,
                 const float* __restrict__ ln_w,
                 const float* __restrict__ ln_b,
                 float* __restrict__ out)
{
    float* xs    = smem + OFF_XS;
    float* wpT   = smem + OFF_WPT;
    float* ws    = smem + OFF_WS;
    float* hs    = smem + OFF_HS;
    float* wdwp  = smem + OFF_WDWP;
    float* qsm   = smem + OFF_Q;
    float* ksm   = smem + OFF_K;
    float* vsm   = smem + OFF_V;
    float* ps    = smem + OFF_PS;
    float* pq    = smem + OFF_PQ;
    float* mean_s = smem + OFF_MEAN;
    float* rstd_s = smem + OFF_RSTD;

    const int t  = threadIdx.x;
    const int bx = blockIdx.x;
    const int by = blockIdx.y;
    const int bb = blockIdx.z;
    const int gx0 = bx * 8 - 1;
    const int gy0 = by * 8 - 1;

    // ---------- stage x tile (10x10 halo, tp=ty*10+tx in slots 0..99) ----------
    for (int idx = t; idx < 64 * 128; idx += THREADS) {
        int ic = idx >> 7, tp = idx & 127;
        float v = 0.f;
        if (tp < 100) {
            int ty = tp / 10, tx = tp - ty * 10;
            int gy = gy0 + ty, gx = gx0 + tx;
            if ((unsigned)gy < IMH && (unsigned)gx < IMW)
                v = x[((size_t)(bb * 64 + ic) * IMH + gy) * IMW + gx];
        }
        xs[idx] = v;
    }

    // 1x1 thread map: pg slow so pixel-padding tail idles whole warps.
    const int pgA = t >> 4;       // 0..31, active < 26 (26*4 = 104 >= 100 px)
    const int cgA = t & 15;       // 0..15: channels cgA*8..cgA*8+7 (of 128/pass)
    const bool activeA = (pgA < 26);
    const int p8 = t & 63;        // patch pixel
    const int i8 = p8 >> 3;
    const int j8 = p8 & 7;
    const int cl8 = t >> 6;       // 0..7 (dw channel group)

    // validity of the 4 tile pixels (SAME-pad: hidden is zero outside image)
    bool vmask[4] = {false, false, false, false};
    if (activeA) {
        #pragma unroll
        for (int l = 0; l < 4; ++l) {
            int tp = pgA * 4 + l;
            if (tp < 100) {
                int ty = tp / 10, tx = tp - ty * 10;
                int gy = gy0 + ty, gx = gx0 + tx;
                vmask[l] = ((unsigned)gy < IMH) && ((unsigned)gx < IMW);
            }
        }
    }

    // ================= Phase A: 3 passes of 128 channels =================
    for (int pass = 0; pass < 3; ++pass) {
        const int pch = pass * 128;
        __syncthreads();
        for (int idx = t; idx < 64 * 128; idx += THREADS) {
            int i = idx & 63, c = idx >> 6;
            ws[i * 132 + c] = w_hidden[(pch + c) * 64 + i];
        }
        for (int idx = t; idx < 128 * 9; idx += THREADS)
            wdwp[idx] = w_dw[pch * 9 + idx];
        __syncthreads();

        // 1x1 conv with packed f32x2: acc[ch j][px-pair pp]
        ull acc[8][2];
        #pragma unroll
        for (int j = 0; j < 8; ++j) {
            float b = __ldg(&b_hidden[pch + cgA * 8 + j]);
            acc[j][0] = pk(b, b);
            acc[j][1] = acc[j][0];
        }
        if (activeA) {
            const float* xsp = xs + pgA * 4;
            const float* wsp = ws + cgA * 8;
            #pragma unroll 4
            for (int i = 0; i < 64; ++i) {
                float4 xv = *(const float4*)(xsp + i * 128);
                ull xp0 = pk(xv.x, xv.y);
                ull xp1 = pk(xv.z, xv.w);
                float4 w0 = *(const float4*)(wsp + i * 132);
                float4 w1 = *(const float4*)(wsp + i * 132 + 4);
                ull wd[8] = {pk(w0.x, w0.x), pk(w0.y, w0.y), pk(w0.z, w0.z), pk(w0.w, w0.w),
                             pk(w1.x, w1.x), pk(w1.y, w1.y), pk(w1.z, w1.z), pk(w1.w, w1.w)};
                #pragma unroll
                for (int j = 0; j < 8; ++j) {
                    acc[j][0] = fma2(xp0, wd[j], acc[j][0]);
                    acc[j][1] = fma2(xp1, wd[j], acc[j][1]);
                }
            }
        }

        float* dst = (pass == 0) ? qsm : (pass == 1) ? ksm : vsm;

        // two 64-channel halves through hs
        #pragma unroll
        for (int h = 0; h < 2; ++h) {
            if (activeA && (cgA >> 3) == h) {
                #pragma unroll
                for (int j = 0; j < 8; ++j) {
                    int lc = (cgA & 7) * 8 + j;
                    float2 a0 = upk(acc[j][0]);
                    float2 a1 = upk(acc[j][1]);
                    float4 hv = make_float4(vmask[0] ? a0.x : 0.f,
                                            vmask[1] ? a0.y : 0.f,
                                            vmask[2] ? a1.x : 0.f,
                                            vmask[3] ? a1.y : 0.f);
                    *(float4*)(hs + lc * 128 + pgA * 4) = hv;
                }
            }
            __syncthreads();

            // depthwise 3x3 on this half -> q/k/v [c][68]
            #pragma unroll
            for (int jj = 0; jj < 8; ++jj) {
                int lc = cl8 * 8 + jj;
                int gc = pch + h * 64 + lc;
                float a = __ldg(&b_dw[gc]);
                const float* hr = hs + lc * 128 + i8 * 10 + j8;
                const float* wd = wdwp + (h * 64 + lc) * 9;
                #pragma unroll
                for (int dy = 0; dy < 3; ++dy)
                    #pragma unroll
                    for (int dx = 0; dx < 3; ++dx)
                        a += hr[dy * 10 + dx] * wd[dy * 3 + dx];
                dst[(h * 64 + lc) * 68 + p8] = a;
            }
            __syncthreads();
        }
    }

    // stage wpT[c][68] = w_proj[o][c]  (overlays dead xs/ws)
    for (int idx = t; idx < 64 * 128; idx += THREADS) {
        int c = idx & 127, o = idx >> 7;
        wpT[c * 68 + o] = w_proj[o * 128 + c];
    }

    // ================= Phase B: circular conv per 8x8 patch (f32x2) =================
    // thread: one channel c, two pixel rows i0, i0+1 packed as f32x2 lanes
    const int lane = t & 31;
    const int warp = t >> 5;
    const int csub = lane >> 2;       // 0..7
    const int pxg  = lane & 3;        // 0..3
    const int c    = warp * 8 + csub; // 0..127
    const int i0   = pxg * 2;

    ull baccp[8];
    #pragma unroll
    for (int j = 0; j < 8; ++j) baccp[j] = 0ull;

    {
        const float* qrow = qsm + c * 68;
        const float* krow = ksm + c * 68;
        #pragma unroll
        for (int a = 0; a < 8; ++a) {
            float4 qa = *(const float4*)(qrow + a * 8);
            float4 qb = *(const float4*)(qrow + a * 8 + 4);
            ull qd[8] = {pk(qa.x, qa.x), pk(qa.y, qa.y), pk(qa.z, qa.z), pk(qa.w, qa.w),
                         pk(qb.x, qb.x), pk(qb.y, qb.y), pk(qb.z, qb.z), pk(qb.w, qb.w)};
            int r0 = (i0 - a) & 7;
            int r1 = (r0 + 1) & 7;
            float4 ka0 = *(const float4*)(krow + r0 * 8);
            float4 ka1 = *(const float4*)(krow + r0 * 8 + 4);
            float4 kb0 = *(const float4*)(krow + r1 * 8);
            float4 kb1 = *(const float4*)(krow + r1 * 8 + 4);
            ull kp[8] = {pk(ka0.x, kb0.x), pk(ka0.y, kb0.y), pk(ka0.z, kb0.z), pk(ka0.w, kb0.w),
                         pk(ka1.x, kb1.x), pk(ka1.y, kb1.y), pk(ka1.z, kb1.z), pk(ka1.w, kb1.w)};
            #pragma unroll
            for (int b = 0; b < 8; ++b) {
                #pragma unroll
                for (int j = 0; j < 8; ++j) {
                    baccp[j] = fma2(qd[b], kp[(j - b) & 7], baccp[j]);
                }
            }
        }
    }
    __syncthreads();

    // unpack + write Phase-B output to osm (= qsm, q is dead) for LN reduction
    float bacc0[8], bacc1[8];
    #pragma unroll
    for (int j = 0; j < 8; ++j) {
        float2 v = upk(baccp[j]);
        bacc0[j] = v.x;
        bacc1[j] = v.y;
        qsm[c * 68 + i0 * 8 + j]       = v.x;
        qsm[c * 68 + (i0 + 1) * 8 + j] = v.y;
    }
    __syncthreads();

    // ---------- LayerNorm stats over 128 channels per pixel ----------
    {
        int px = t & 63, g = t >> 6;    // g: 16-channel group
        float s = 0.f, ss = 0.f;
        #pragma unroll 4
        for (int cc = g * 16; cc < g * 16 + 16; ++cc) {
            float v = qsm[cc * 68 + px];
            s += v; ss += v * v;
        }
        ps[g * 66 + px] = s;
        pq[g * 66 + px] = ss;
    }
    __syncthreads();
    if (t < 64) {
        float sm = 0.f, sq = 0.f;
        #pragma unroll
        for (int g = 0; g < 8; ++g) { sm += ps[g * 66 + t]; sq += pq[g * 66 + t]; }
        float mu  = sm * (1.f / 128.f);
        float var = sq * (1.f / 128.f) - mu * mu;
        mean_s[t] = mu;
        rstd_s[t] = rsqrtf(var + 1e-5f);
    }
    __syncthreads();

    // ---------- normalize, scale/shift, multiply by v -> ovsm (= ksm, k dead) ----------
    {
        float lw = __ldg(&ln_w[c]);
        float lb = __ldg(&ln_b[c]);
        #pragma unroll
        for (int di = 0; di < 2; ++di) {
            int row = i0 + di;
            float4 v0 = *(const float4*)(vsm + c * 68 + row * 8);
            float4 v1 = *(const float4*)(vsm + c * 68 + row * 8 + 4);
            float vv[8] = {v0.x, v0.y, v0.z, v0.w, v1.x, v1.y, v1.z, v1.w};
            const float* ba = (di == 0) ? bacc0 : bacc1;
            float ov[8];
            #pragma unroll
            for (int j = 0; j < 8; ++j) {
                int px = row * 8 + j;
                float o = (ba[j] - mean_s[px]) * rstd_s[px] * lw + lb;
                ov[j] = vv[j] * o;
            }
            *(float4*)(ksm + c * 68 + row * 8)     = make_float4(ov[0], ov[1], ov[2], ov[3]);
            *(float4*)(ksm + c * 68 + row * 8 + 4) = make_float4(ov[4], ov[5], ov[6], ov[7]);
        }
    }
    __syncthreads();

    // ---------- 1x1 projection 128 -> 64 (f32x2, paired outputs) ----------
    {
        const int og = t >> 6;   // 0..7: outputs og*8..og*8+7
        ull rp[4];
        #pragma unroll
        for (int k = 0; k < 4; ++k)
            rp[k] = pk(__ldg(&b_proj[og * 8 + 2 * k]), __ldg(&b_proj[og * 8 + 2 * k + 1]));

        #pragma unroll 8
        for (int cc = 0; cc < 128; ++cc) {
            float ov = ksm[cc * 68 + p8];
            ull ovd = pk(ov, ov);
            float4 w0 = *(const float4*)(wpT + cc * 68 + og * 8);
            float4 w1 = *(const float4*)(wpT + cc * 68 + og * 8 + 4);
            ull wp0 = pk(w0.x, w0.y), wp1 = pk(w0.z, w0.w);
            ull wp2 = pk(w1.x, w1.y), wp3 = pk(w1.z, w1.w);
            rp[0] = fma2(ovd, wp0, rp[0]);
            rp[1] = fma2(ovd, wp1, rp[1]);
            rp[2] = fma2(ovd, wp2, rp[2]);
            rp[3] = fma2(ovd, wp3, rp[3]);
        }

        const int gy = by * 8 + i8;
        const int gx = bx * 8 + j8;
        #pragma unroll
        for (int k = 0; k < 4; ++k) {
            float2 r = upk(rp[k]);
            int o = og * 8 + 2 * k;
            out[((size_t)(bb * 64 + o) * IMH + gy) * IMW + gx]       = r.x;
            out[((size_t)(bb * 64 + o + 1) * IMH + gy) * IMW + gx]   = r.y;
        }
    }
}

extern "C" void kernel_launch(void* const* d_in, const int* in_sizes, int n_in,
                              void* d_out, int out_size) {
    const float* x        = (const float*)d_in[0];
    const float* w_hidden = (const float*)d_in[1];
    const float* b_hidden = (const float*)d_in[2];
    const float* w_dw     = (const float*)d_in[3];
    const float* b_dw     = (const float*)d_in[4];
    const float* w_proj   = (const float*)d_in[5];
    const float* b_proj   = (const float*)d_in[6];
    const float* ln_w     = (const float*)d_in[7];
    const float* ln_b     = (const float*)d_in[8];
    float* out = (float*)d_out;

    const int smem_bytes = SMEM_FLOATS * sizeof(float);  // 213120 B
    cudaFuncSetAttribute(fsas_kernel, cudaFuncAttributeMaxDynamicSharedMemorySize, smem_bytes);

    dim3 grid(32, 32, 4);
    fsas_kernel<<<grid, THREADS, smem_bytes>>>(x, w_hidden, b_hidden, w_dw, b_dw,
                                               w_proj, b_proj, ln_w, ln_b, out);
}

// round 5
// speedup vs baseline: 1.0484x; 1.0484x over previous
#include <cuda_runtime.h>

#define THREADS 512
#define IMH 256
#define IMW 256

// shared memory offsets (floats)
#define OFF_XS    0          // [64][128] x tile; overlaid by wpT[128][68] after Phase A
#define OFF_WPT   0
#define OFF_WS    8192       // [64][132] staged w_hidden pass chunk, transposed
#define OFF_HS    16640      // [64][128] hidden scratch (one 64-ch half)
#define OFF_WDWP  24832      // [128][9] dw weights for pass
#define OFF_Q     25984      // [128][68]
#define OFF_K     34688      // [128][68]
#define OFF_V     43392      // [128][68]
#define OFF_PS    52096      // [8][66]
#define OFF_PQ    52624      // [8][66]
#define OFF_MEAN  53152      // [64]
#define OFF_RSTD  53216      // [64]
#define SMEM_FLOATS 53280    // 213120 bytes

extern __shared__ float smem[];

__global__ __launch_bounds__(THREADS, 1)
void fsas_kernel(const float* __restrict__ x,
                 const float* __restrict__ w_hidden,
                 const float* __restrict__ b_hidden,
                 const float* __restrict__ w_dw,
                 const float* __restrict__ b_dw,
                 const float* __restrict__ w_proj,
                 const float* __restrict__ b_proj,
                 const float* __restrict__ ln_w,
                 const float* __restrict__ ln_b,
                 float* __restrict__ out)
{
    float* xs    = smem + OFF_XS;
    float* wpT   = smem + OFF_WPT;
    float* ws    = smem + OFF_WS;
    float* hs    = smem + OFF_HS;
    float* wdwp  = smem + OFF_WDWP;
    float* qsm   = smem + OFF_Q;
    float* ksm   = smem + OFF_K;
    float* vsm   = smem + OFF_V;
    float* ps    = smem + OFF_PS;
    float* pq    = smem + OFF_PQ;
    float* mean_s = smem + OFF_MEAN;
    float* rstd_s = smem + OFF_RSTD;

    const int t  = threadIdx.x;
    const int bx = blockIdx.x;
    const int by = blockIdx.y;
    const int bb = blockIdx.z;
    const int gx0 = bx * 8 - 1;
    const int gy0 = by * 8 - 1;

    // ---------- stage x tile (10x10 halo, tp=ty*10+tx in slots 0..99) ----------
    for (int idx = t; idx < 64 * 128; idx += THREADS) {
        int ic = idx >> 7, tp = idx & 127;
        float v = 0.f;
        if (tp < 100) {
            int ty = tp / 10, tx = tp - ty * 10;
            int gy = gy0 + ty, gx = gx0 + tx;
            if ((unsigned)gy < IMH && (unsigned)gx < IMW)
                v = x[((size_t)(bb * 64 + ic) * IMH + gy) * IMW + gx];
        }
        xs[idx] = v;
    }

    // Phase A map: pg slow-varying so padding tail idles whole warps.
    // pgA 0..24 active covers exactly pixels 0..99.
    const int pgA = t >> 4;       // 0..31, active < 25
    const int cgA = t & 15;       // 0..15: channels cgA*8..cgA*8+7 (of 128/pass)
    const bool activeA = (pgA < 25);
    const int p8 = t & 63;        // patch pixel
    const int i8 = p8 >> 3;
    const int j8 = p8 & 7;
    const int cl8 = t >> 6;       // 0..7 (dw channel group)

    // validity of the 4 tile pixels (SAME-pad: hidden is zero outside image)
    bool vmask[4] = {false, false, false, false};
    if (activeA) {
        #pragma unroll
        for (int l = 0; l < 4; ++l) {
            int tp = pgA * 4 + l;
            if (tp < 100) {
                int ty = tp / 10, tx = tp - ty * 10;
                int gy = gy0 + ty, gx = gx0 + tx;
                vmask[l] = ((unsigned)gy < IMH) && ((unsigned)gx < IMW);
            }
        }
    }

    // ================= Phase A: 3 passes of 128 channels =================
    for (int pass = 0; pass < 3; ++pass) {
        const int pch = pass * 128;
        __syncthreads();
        // stage ws[i][c] = w_hidden[pch+c][i], row stride 132
        for (int idx = t; idx < 64 * 128; idx += THREADS) {
            int i = idx & 63, c = idx >> 6;
            ws[i * 132 + c] = w_hidden[(pch + c) * 64 + i];
        }
        // stage dw weights for this pass
        for (int idx = t; idx < 128 * 9; idx += THREADS)
            wdwp[idx] = w_dw[pch * 9 + idx];
        __syncthreads();

        // 1x1 conv: acc[ch j][px l]
        float acc[8][4];
        #pragma unroll
        for (int j = 0; j < 8; ++j) {
            float b = __ldg(&b_hidden[pch + cgA * 8 + j]);
            acc[j][0] = b; acc[j][1] = b; acc[j][2] = b; acc[j][3] = b;
        }
        if (activeA) {
            const float* xsp = xs + pgA * 4;
            const float* wsp = ws + cgA * 8;
            #pragma unroll 4
            for (int i = 0; i < 64; ++i) {
                float4 xv = *(const float4*)(xsp + i * 128);
                float4 w0 = *(const float4*)(wsp + i * 132);
                float4 w1 = *(const float4*)(wsp + i * 132 + 4);
                float wv[8] = {w0.x, w0.y, w0.z, w0.w, w1.x, w1.y, w1.z, w1.w};
                #pragma unroll
                for (int j = 0; j < 8; ++j) {
                    acc[j][0] += wv[j] * xv.x;
                    acc[j][1] += wv[j] * xv.y;
                    acc[j][2] += wv[j] * xv.z;
                    acc[j][3] += wv[j] * xv.w;
                }
            }
        }

        float* dst = (pass == 0) ? qsm : (pass == 1) ? ksm : vsm;

        // two 64-channel halves through hs
        #pragma unroll
        for (int h = 0; h < 2; ++h) {
            if (activeA && (cgA >> 3) == h) {
                #pragma unroll
                for (int j = 0; j < 8; ++j) {
                    int lc = (cgA & 7) * 8 + j;
                    float4 hv = make_float4(vmask[0] ? acc[j][0] : 0.f,
                                            vmask[1] ? acc[j][1] : 0.f,
                                            vmask[2] ? acc[j][2] : 0.f,
                                            vmask[3] ? acc[j][3] : 0.f);
                    *(float4*)(hs + lc * 128 + pgA * 4) = hv;
                }
            }
            __syncthreads();

            // depthwise 3x3 on this half -> q/k/v [c][68]
            #pragma unroll
            for (int jj = 0; jj < 8; ++jj) {
                int lc = cl8 * 8 + jj;
                int gc = pch + h * 64 + lc;
                float a = __ldg(&b_dw[gc]);
                const float* hr = hs + lc * 128 + i8 * 10 + j8;
                const float* wd = wdwp + (h * 64 + lc) * 9;
                #pragma unroll
                for (int dy = 0; dy < 3; ++dy)
                    #pragma unroll
                    for (int dx = 0; dx < 3; ++dx)
                        a += hr[dy * 10 + dx] * wd[dy * 3 + dx];
                dst[(h * 64 + lc) * 68 + p8] = a;
            }
            __syncthreads();
        }
    }

    // stage wpT[c][68] = w_proj[o][c]  (overlays dead xs/ws)
    for (int idx = t; idx < 64 * 128; idx += THREADS) {
        int c = idx & 127, o = idx >> 7;
        wpT[c * 68 + o] = w_proj[o * 128 + c];
    }
    // note: syncs below before proj reads wpT

    // ================= Phase B: circular conv per 8x8 patch =================
    // thread: one channel c, two pixel rows i0, i0+1
    const int lane = t & 31;
    const int warp = t >> 5;
    const int csub = lane >> 2;       // 0..7
    const int pxg  = lane & 3;        // 0..3
    const int c    = warp * 8 + csub; // 0..127
    const int i0   = pxg * 2;

    float bacc[2][8];
    #pragma unroll
    for (int di = 0; di < 2; ++di)
        #pragma unroll
        for (int j = 0; j < 8; ++j) bacc[di][j] = 0.f;

    {
        const float* qrow = qsm + c * 68;
        const float* krow = ksm + c * 68;
        #pragma unroll
        for (int a = 0; a < 8; ++a) {
            float4 qa = *(const float4*)(qrow + a * 8);
            float4 qb = *(const float4*)(qrow + a * 8 + 4);
            float qq[8] = {qa.x, qa.y, qa.z, qa.w, qb.x, qb.y, qb.z, qb.w};
            int r0 = (i0 - a) & 7;
            int r1 = (r0 + 1) & 7;
            float4 ka0 = *(const float4*)(krow + r0 * 8);
            float4 ka1 = *(const float4*)(krow + r0 * 8 + 4);
            float4 kb0 = *(const float4*)(krow + r1 * 8);
            float4 kb1 = *(const float4*)(krow + r1 * 8 + 4);
            float k0[8] = {ka0.x, ka0.y, ka0.z, ka0.w, ka1.x, ka1.y, ka1.z, ka1.w};
            float k1[8] = {kb0.x, kb0.y, kb0.z, kb0.w, kb1.x, kb1.y, kb1.z, kb1.w};
            #pragma unroll
            for (int b = 0; b < 8; ++b) {
                #pragma unroll
                for (int j = 0; j < 8; ++j) {
                    int kc = (j - b) & 7;
                    bacc[0][j] += qq[b] * k0[kc];
                    bacc[1][j] += qq[b] * k1[kc];
                }
            }
        }
    }
    __syncthreads();

    // write Phase-B output to osm (= qsm, q is dead) for the LN reduction
    #pragma unroll
    for (int di = 0; di < 2; ++di) {
        int row = i0 + di;
        *(float4*)(qsm + c * 68 + row * 8)     = make_float4(bacc[di][0], bacc[di][1], bacc[di][2], bacc[di][3]);
        *(float4*)(qsm + c * 68 + row * 8 + 4) = make_float4(bacc[di][4], bacc[di][5], bacc[di][6], bacc[di][7]);
    }
    __syncthreads();

    // ---------- LayerNorm stats over 128 channels per pixel ----------
    {
        int px = t & 63, g = t >> 6;    // g: 16-channel group
        float s = 0.f, ss = 0.f;
        #pragma unroll 4
        for (int cc = g * 16; cc < g * 16 + 16; ++cc) {
            float v = qsm[cc * 68 + px];
            s += v; ss += v * v;
        }
        ps[g * 66 + px] = s;
        pq[g * 66 + px] = ss;
    }
    __syncthreads();
    if (t < 64) {
        float sm = 0.f, sq = 0.f;
        #pragma unroll
        for (int g = 0; g < 8; ++g) { sm += ps[g * 66 + t]; sq += pq[g * 66 + t]; }
        float mu  = sm * (1.f / 128.f);
        float var = sq * (1.f / 128.f) - mu * mu;
        mean_s[t] = mu;
        rstd_s[t] = rsqrtf(var + 1e-5f);
    }
    __syncthreads();

    // ---------- normalize, scale/shift, multiply by v -> ovsm (= ksm, k dead) ----------
    {
        float lw = __ldg(&ln_w[c]);
        float lb = __ldg(&ln_b[c]);
        #pragma unroll
        for (int di = 0; di < 2; ++di) {
            int row = i0 + di;
            float4 v0 = *(const float4*)(vsm + c * 68 + row * 8);
            float4 v1 = *(const float4*)(vsm + c * 68 + row * 8 + 4);
            float vv[8] = {v0.x, v0.y, v0.z, v0.w, v1.x, v1.y, v1.z, v1.w};
            float ov[8];
            #pragma unroll
            for (int j = 0; j < 8; ++j) {
                int px = row * 8 + j;
                float o = (bacc[di][j] - mean_s[px]) * rstd_s[px] * lw + lb;
                ov[j] = vv[j] * o;
            }
            *(float4*)(ksm + c * 68 + row * 8)     = make_float4(ov[0], ov[1], ov[2], ov[3]);
            *(float4*)(ksm + c * 68 + row * 8 + 4) = make_float4(ov[4], ov[5], ov[6], ov[7]);
        }
    }
    __syncthreads();

    // ---------- 1x1 projection 128 -> 64 ----------
    {
        const int og = t >> 6;   // 0..7: outputs og*8..og*8+7
        float r[8];
        #pragma unroll
        for (int j = 0; j < 8; ++j) r[j] = __ldg(&b_proj[og * 8 + j]);

        #pragma unroll 8
        for (int cc = 0; cc < 128; ++cc) {
            float ov = ksm[cc * 68 + p8];
            float4 w0 = *(const float4*)(wpT + cc * 68 + og * 8);
            float4 w1 = *(const float4*)(wpT + cc * 68 + og * 8 + 4);
            r[0] += ov * w0.x;  r[1] += ov * w0.y;
            r[2] += ov * w0.z;  r[3] += ov * w0.w;
            r[4] += ov * w1.x;  r[5] += ov * w1.y;
            r[6] += ov * w1.z;  r[7] += ov * w1.w;
        }

        const int gy = by * 8 + i8;
        const int gx = bx * 8 + j8;
        #pragma unroll
        for (int j = 0; j < 8; ++j) {
            int o = og * 8 + j;
            out[((size_t)(bb * 64 + o) * IMH + gy) * IMW + gx] = r[j];
        }
    }
}

extern "C" void kernel_launch(void* const* d_in, const int* in_sizes, int n_in,
                              void* d_out, int out_size) {
    const float* x        = (const float*)d_in[0];
    const float* w_hidden = (const float*)d_in[1];
    const float* b_hidden = (const float*)d_in[2];
    const float* w_dw     = (const float*)d_in[3];
    const float* b_dw     = (const float*)d_in[4];
    const float* w_proj   = (const float*)d_in[5];
    const float* b_proj   = (const float*)d_in[6];
    const float* ln_w     = (const float*)d_in[7];
    const float* ln_b     = (const float*)d_in[8];
    float* out = (float*)d_out;

    const int smem_bytes = SMEM_FLOATS * sizeof(float);  // 213120 B
    cudaFuncSetAttribute(fsas_kernel, cudaFuncAttributeMaxDynamicSharedMemorySize, smem_bytes);

    dim3 grid(32, 32, 4);
    fsas_kernel<<<grid, THREADS, smem_bytes>>>(x, w_hidden, b_hidden, w_dw, b_dw,
                                               w_proj, b_proj, ln_w, ln_b, out);
}

// round 6
// speedup vs baseline: 1.4230x; 1.3573x over previous
#include <cuda_runtime.h>

#define THREADS 1024
#define IMH 256
#define IMW 256

// shared memory offsets (floats)
#define OFF_XS    0          // [64][128] x tile; overlaid by wpT[128][68] after Phase A
#define OFF_WPT   0
#define OFF_WS    8192       // [64][132] staged w_hidden pass chunk, transposed [i][c]
#define OFF_HS    16640      // [100][68] hidden scratch (one 64-ch half), [pixel][ch]
#define OFF_WDWT  23440      // [9][132] dw weights transposed [tap][ch]
#define OFF_Q     24640      // [128][68]
#define OFF_K     33344      // [128][68]
#define OFF_V     42048      // [128][68]
#define OFF_PS    50752      // [16][66]
#define OFF_PQ    51808      // [16][66]
#define OFF_MEAN  52864      // [64]
#define OFF_RSTD  52928      // [64]
#define SMEM_FLOATS 52992    // 211968 bytes

extern __shared__ float smem[];

__global__ __launch_bounds__(THREADS, 1)
void fsas_kernel(const float* __restrict__ x,
                 const float* __restrict__ w_hidden,
                 const float* __restrict__ b_hidden,
                 const float* __restrict__ w_dw,
                 const float* __restrict__ b_dw,
                 const float* __restrict__ w_proj,
                 const float* __restrict__ b_proj,
                 const float* __restrict__ ln_w,
                 const float* __restrict__ ln_b,
                 float* __restrict__ out)
{
    float* xs    = smem + OFF_XS;
    float* wpT   = smem + OFF_WPT;
    float* ws    = smem + OFF_WS;
    float* hs    = smem + OFF_HS;
    float* wdwT  = smem + OFF_WDWT;
    float* qsm   = smem + OFF_Q;
    float* ksm   = smem + OFF_K;
    float* vsm   = smem + OFF_V;
    float* ps    = smem + OFF_PS;
    float* pq    = smem + OFF_PQ;
    float* mean_s = smem + OFF_MEAN;
    float* rstd_s = smem + OFF_RSTD;

    const int t  = threadIdx.x;
    const int bx = blockIdx.x;
    const int by = blockIdx.y;
    const int bb = blockIdx.z;
    const int gx0 = bx * 8 - 1;
    const int gy0 = by * 8 - 1;

    // ---------- stage x tile (10x10 halo, tp=ty*10+tx in slots 0..99) ----------
    for (int idx = t; idx < 64 * 128; idx += THREADS) {
        int ic = idx >> 7, tp = idx & 127;
        float v = 0.f;
        if (tp < 100) {
            int ty = tp / 10, tx = tp - ty * 10;
            int gy = gy0 + ty, gx = gx0 + tx;
            if ((unsigned)gy < IMH && (unsigned)gx < IMW)
                v = x[((size_t)(bb * 64 + ic) * IMH + gy) * IMW + gx];
        }
        xs[idx] = v;
    }

    // Phase A map: warp = pixel group (4 px), lane = 4 channels of 128/pass.
    const int w  = t >> 5;        // warp 0..31, active < 25 (covers px 0..99)
    const int l  = t & 31;        // lane: channels l*4..l*4+3
    const bool activeA = (w < 25);

    const int p8 = t & 63;        // patch pixel (dw / LN-stats / proj maps)
    const int i8 = p8 >> 3;
    const int j8 = p8 & 7;
    const int clg = t >> 6;       // 0..15: dw/proj channel-or-output group (x4)

    // validity of this warp's 4 tile pixels (SAME-pad: hidden zero outside image)
    bool vmask[4] = {false, false, false, false};
    if (activeA) {
        #pragma unroll
        for (int p = 0; p < 4; ++p) {
            int tp = w * 4 + p;
            int ty = tp / 10, tx = tp - ty * 10;
            int gy = gy0 + ty, gx = gx0 + tx;
            vmask[p] = ((unsigned)gy < IMH) && ((unsigned)gx < IMW);
        }
    }

    // ================= Phase A: 3 passes of 128 channels =================
    for (int pass = 0; pass < 3; ++pass) {
        const int pch = pass * 128;
        __syncthreads();
        // stage ws[i][c] = w_hidden[pch+c][i], row stride 132
        for (int idx = t; idx < 64 * 128; idx += THREADS) {
            int i = idx & 63, c = idx >> 6;
            ws[i * 132 + c] = w_hidden[(pch + c) * 64 + i];
        }
        // stage dw weights transposed: wdwT[tap][c]
        for (int idx = t; idx < 128 * 9; idx += THREADS) {
            int c = idx / 9, tap = idx - c * 9;
            wdwT[tap * 132 + c] = w_dw[pch * 9 + idx];
        }
        __syncthreads();

        // 1x1 conv: acc[ch j][px p]; xv broadcast, weights contiguous LDS.128
        float acc[4][4];
        #pragma unroll
        for (int j = 0; j < 4; ++j) {
            float b = __ldg(&b_hidden[pch + l * 4 + j]);
            acc[j][0] = b; acc[j][1] = b; acc[j][2] = b; acc[j][3] = b;
        }
        if (activeA) {
            const float* xsp = xs + w * 4;
            const float* wsp = ws + l * 4;
            #pragma unroll 4
            for (int i = 0; i < 64; ++i) {
                float4 xv = *(const float4*)(xsp + i * 128);
                float4 wv = *(const float4*)(wsp + i * 132);
                acc[0][0] += wv.x * xv.x; acc[0][1] += wv.x * xv.y;
                acc[0][2] += wv.x * xv.z; acc[0][3] += wv.x * xv.w;
                acc[1][0] += wv.y * xv.x; acc[1][1] += wv.y * xv.y;
                acc[1][2] += wv.y * xv.z; acc[1][3] += wv.y * xv.w;
                acc[2][0] += wv.z * xv.x; acc[2][1] += wv.z * xv.y;
                acc[2][2] += wv.z * xv.z; acc[2][3] += wv.z * xv.w;
                acc[3][0] += wv.w * xv.x; acc[3][1] += wv.w * xv.y;
                acc[3][2] += wv.w * xv.z; acc[3][3] += wv.w * xv.w;
            }
        }

        float* dst = (pass == 0) ? qsm : (pass == 1) ? ksm : vsm;

        // two 64-channel halves through hs[pixel][68ch]
        #pragma unroll
        for (int h = 0; h < 2; ++h) {
            if (activeA && (l >> 4) == h) {
                const int lc4 = (l & 15) * 4;
                #pragma unroll
                for (int p = 0; p < 4; ++p) {
                    float4 hv = make_float4(vmask[p] ? acc[0][p] : 0.f,
                                            vmask[p] ? acc[1][p] : 0.f,
                                            vmask[p] ? acc[2][p] : 0.f,
                                            vmask[p] ? acc[3][p] : 0.f);
                    *(float4*)(hs + (w * 4 + p) * 68 + lc4) = hv;
                }
            }
            __syncthreads();

            // depthwise 3x3 on this half -> q/k/v [c][68]
            {
                float a4[4];
                #pragma unroll
                for (int j = 0; j < 4; ++j)
                    a4[j] = __ldg(&b_dw[pch + h * 64 + clg * 4 + j]);
                const float* hbase = hs + (i8 * 10 + j8) * 68 + clg * 4;
                const float* wbase = wdwT + h * 64 + clg * 4;
                #pragma unroll
                for (int dy = 0; dy < 3; ++dy) {
                    #pragma unroll
                    for (int dx = 0; dx < 3; ++dx) {
                        float4 hv = *(const float4*)(hbase + (dy * 10 + dx) * 68);
                        float4 wv = *(const float4*)(wbase + (dy * 3 + dx) * 132);
                        a4[0] += hv.x * wv.x;
                        a4[1] += hv.y * wv.y;
                        a4[2] += hv.z * wv.z;
                        a4[3] += hv.w * wv.w;
                    }
                }
                #pragma unroll
                for (int j = 0; j < 4; ++j)
                    dst[(h * 64 + clg * 4 + j) * 68 + p8] = a4[j];
            }
            __syncthreads();
        }
    }

    // stage wpT[c][68] = w_proj[o][c]  (overlays dead xs/ws)
    for (int idx = t; idx < 64 * 128; idx += THREADS) {
        int c = idx & 127, o = idx >> 7;
        wpT[c * 68 + o] = w_proj[o * 128 + c];
    }
    // syncs below before proj reads wpT

    // ================= Phase B: circular conv per 8x8 patch =================
    // thread: one channel c, one pixel row
    const int c   = t >> 3;       // 0..127
    const int row = t & 7;        // 0..7

    float bacc[8];
    #pragma unroll
    for (int j = 0; j < 8; ++j) bacc[j] = 0.f;

    {
        const float* qrow = qsm + c * 68;
        const float* krow = ksm + c * 68;
        #pragma unroll
        for (int a = 0; a < 8; ++a) {
            float4 qa = *(const float4*)(qrow + a * 8);
            float4 qb = *(const float4*)(qrow + a * 8 + 4);
            float qq[8] = {qa.x, qa.y, qa.z, qa.w, qb.x, qb.y, qb.z, qb.w};
            int r0 = (row - a) & 7;
            float4 k0 = *(const float4*)(krow + r0 * 8);
            float4 k1 = *(const float4*)(krow + r0 * 8 + 4);
            float kk[8] = {k0.x, k0.y, k0.z, k0.w, k1.x, k1.y, k1.z, k1.w};
            #pragma unroll
            for (int b = 0; b < 8; ++b) {
                #pragma unroll
                for (int j = 0; j < 8; ++j)
                    bacc[j] += qq[b] * kk[(j - b) & 7];
            }
        }
    }
    __syncthreads();

    // write Phase-B output to qsm (q dead) for the LN reduction
    *(float4*)(qsm + c * 68 + row * 8)     = make_float4(bacc[0], bacc[1], bacc[2], bacc[3]);
    *(float4*)(qsm + c * 68 + row * 8 + 4) = make_float4(bacc[4], bacc[5], bacc[6], bacc[7]);
    __syncthreads();

    // ---------- LayerNorm stats over 128 channels per pixel ----------
    {
        // px = p8, group g = clg: 8 channels each
        float s = 0.f, ss = 0.f;
        #pragma unroll
        for (int u = 0; u < 8; ++u) {
            float v = qsm[(clg * 8 + u) * 68 + p8];
            s += v; ss += v * v;
        }
        ps[clg * 66 + p8] = s;
        pq[clg * 66 + p8] = ss;
    }
    __syncthreads();
    if (t < 64) {
        float sm = 0.f, sq = 0.f;
        #pragma unroll
        for (int g = 0; g < 16; ++g) { sm += ps[g * 66 + t]; sq += pq[g * 66 + t]; }
        float mu  = sm * (1.f / 128.f);
        float var = sq * (1.f / 128.f) - mu * mu;
        mean_s[t] = mu;
        rstd_s[t] = rsqrtf(var + 1e-5f);
    }
    __syncthreads();

    // ---------- normalize, scale/shift, multiply by v -> ksm (k dead) ----------
    {
        float lw = __ldg(&ln_w[c]);
        float lb = __ldg(&ln_b[c]);
        float4 v0 = *(const float4*)(vsm + c * 68 + row * 8);
        float4 v1 = *(const float4*)(vsm + c * 68 + row * 8 + 4);
        float vv[8] = {v0.x, v0.y, v0.z, v0.w, v1.x, v1.y, v1.z, v1.w};
        float ov[8];
        #pragma unroll
        for (int j = 0; j < 8; ++j) {
            int px = row * 8 + j;
            float o = (bacc[j] - mean_s[px]) * rstd_s[px] * lw + lb;
            ov[j] = vv[j] * o;
        }
        *(float4*)(ksm + c * 68 + row * 8)     = make_float4(ov[0], ov[1], ov[2], ov[3]);
        *(float4*)(ksm + c * 68 + row * 8 + 4) = make_float4(ov[4], ov[5], ov[6], ov[7]);
    }
    __syncthreads();

    // ---------- 1x1 projection 128 -> 64 ----------
    {
        // thread: pixel p8, outputs clg*4..clg*4+3
        float r[4];
        #pragma unroll
        for (int j = 0; j < 4; ++j) r[j] = __ldg(&b_proj[clg * 4 + j]);

        #pragma unroll 8
        for (int cc = 0; cc < 128; ++cc) {
            float ov = ksm[cc * 68 + p8];
            float4 wv = *(const float4*)(wpT + cc * 68 + clg * 4);
            r[0] += ov * wv.x;  r[1] += ov * wv.y;
            r[2] += ov * wv.z;  r[3] += ov * wv.w;
        }

        const int gy = by * 8 + i8;
        const int gx = bx * 8 + j8;
        #pragma unroll
        for (int j = 0; j < 4; ++j) {
            int o = clg * 4 + j;
            out[((size_t)(bb * 64 + o) * IMH + gy) * IMW + gx] = r[j];
        }
    }
}

extern "C" void kernel_launch(void* const* d_in, const int* in_sizes, int n_in,
                              void* d_out, int out_size) {
    const float* x        = (const float*)d_in[0];
    const float* w_hidden = (const float*)d_in[1];
    const float* b_hidden = (const float*)d_in[2];
    const float* w_dw     = (const float*)d_in[3];
    const float* b_dw     = (const float*)d_in[4];
    const float* w_proj   = (const float*)d_in[5];
    const float* b_proj   = (const float*)d_in[6];
    const float* ln_w     = (const float*)d_in[7];
    const float* ln_b     = (const float*)d_in[8];
    float* out = (float*)d_out;

    const int smem_bytes = SMEM_FLOATS * sizeof(float);  // 211968 B
    cudaFuncSetAttribute(fsas_kernel, cudaFuncAttributeMaxDynamicSharedMemorySize, smem_bytes);

    dim3 grid(32, 32, 4);
    fsas_kernel<<<grid, THREADS, smem_bytes>>>(x, w_hidden, b_hidden, w_dw, b_dw,
                                               w_proj, b_proj, ln_w, ln_b, out);
}